// round 6
// baseline (speedup 1.0000x reference)
#include <cuda_runtime.h>
#include <cstdint>

// QuantizedEmbedding R6: warp-autonomous TMA-store pipeline (R5) +
//  - __launch_bounds__(256,7): force regs<=36 so 7 CTAs/SM (smem ceiling)
//  - CTA's 4 token indices loaded as one int4 up front (no per-iter index chase)
//  - dequant directly into smem stores to trim live registers

static constexpr int PACKED   = 2048;    // packed int32 per row
static constexpr int NGROUPS  = 128;
static constexpr int DIM      = 4096;
static constexpr int THREADS  = 256;     // thread t: packed [t*8, t*8+8) -> group t>>1
static constexpr int TOKS     = 4;       // tokens per CTA (grid 4096)
static constexpr int WARPS    = THREADS / 32;
static constexpr int SLICE_F  = DIM / WARPS;           // 512 floats = 2KB per warp slice
static constexpr int SLICE_B  = SLICE_F * 4;           // 2048 bytes
static constexpr int SMEM_BYTES = WARPS * 2 * SLICE_B; // 32KB

__device__ __forceinline__ float4 dq2(int a, int b, float s) {
    float4 r;
    r.x = (float)(a / 16 - 8) * s;       // trunc-toward-zero high nibble
    r.y = (float)((a & 15) - 8) * s;     // nonneg mod-16 low nibble
    r.z = (float)(b / 16 - 8) * s;
    r.w = (float)((b & 15) - 8) * s;
    return r;
}

__global__ void __launch_bounds__(THREADS, 7)
qemb_kernel(const int* __restrict__ indices,
            const int* __restrict__ weight,
            const float* __restrict__ scales,
            float* __restrict__ out,
            int n_tokens)
{
    extern __shared__ float4 buf[];   // [WARPS][2][SLICE_F/4]
    int t    = threadIdx.x;
    int warp = t >> 5;
    int lane = t & 31;
    long base = (long)blockIdx.x * TOKS;

    // all 4 token indices in one load (n_tokens = 16384 is a multiple of TOKS)
    int4 idx4 = __ldg(reinterpret_cast<const int4*>(indices + base));
    int idxs[TOKS] = { idx4.x, idx4.y, idx4.z, idx4.w };

    float4* wbuf = buf + (size_t)warp * 2 * (SLICE_F / 4);

    // prefetch token 0
    const int4* wrow = reinterpret_cast<const int4*>(weight + (long)idxs[0] * PACKED) + t * 2;
    int4 w0 = __ldg(wrow);
    int4 w1 = __ldg(wrow + 1);
    float s = __ldg(scales + (long)idxs[0] * NGROUPS + (t >> 1));

    #pragma unroll
    for (int i = 0; i < TOKS; i++) {
        // prefetch token i+1 (independent of anything below)
        int4 n0, n1; float ns;
        if (i + 1 < TOKS) {
            const int4* wrow2 =
                reinterpret_cast<const int4*>(weight + (long)idxs[i + 1] * PACKED) + t * 2;
            n0 = __ldg(wrow2);
            n1 = __ldg(wrow2 + 1);
            ns = __ldg(scales + (long)idxs[i + 1] * NGROUPS + (t >> 1));
        }

        // buffer (i&1) reuse guard: its store was committed at iter i-2
        if (i >= 2 && lane == 0)
            asm volatile("cp.async.bulk.wait_group %0;" :: "n"(1) : "memory");
        __syncwarp();

        // dequant straight into smem (lane stores 4 consecutive float4 = 64B)
        float4* b = wbuf + (size_t)(i & 1) * (SLICE_F / 4) + lane * 4;
        b[0] = dq2(w0.x, w0.y, s);
        b[1] = dq2(w0.z, w0.w, s);
        b[2] = dq2(w1.x, w1.y, s);
        b[3] = dq2(w1.z, w1.w, s);

        asm volatile("fence.proxy.async.shared::cta;" ::: "memory");
        __syncwarp();

        if (lane == 0) {
            uint32_t saddr = (uint32_t)__cvta_generic_to_shared(
                wbuf + (size_t)(i & 1) * (SLICE_F / 4));
            void* g = (void*)(out + (base + i) * DIM + warp * SLICE_F);
            asm volatile("cp.async.bulk.global.shared::cta.bulk_group [%0], [%1], %2;"
                         :: "l"(g), "r"(saddr), "n"(SLICE_B) : "memory");
            asm volatile("cp.async.bulk.commit_group;" ::: "memory");
        }

        w0 = n0; w1 = n1; s = ns;
    }

    if (lane == 0)
        asm volatile("cp.async.bulk.wait_group 0;" ::: "memory");
}

extern "C" void kernel_launch(void* const* d_in, const int* in_sizes, int n_in,
                              void* d_out, int out_size)
{
    const int*   indices = (const int*)d_in[0];
    const int*   weight  = (const int*)d_in[1];
    const float* scales  = (const float*)d_in[2];
    float*       out     = (float*)d_out;

    int n_tokens = in_sizes[0];  // 16384

    cudaFuncSetAttribute(qemb_kernel,
                         cudaFuncAttributeMaxDynamicSharedMemorySize, SMEM_BYTES);

    int grid = (n_tokens + TOKS - 1) / TOKS;  // 4096
    qemb_kernel<<<grid, THREADS, SMEM_BYTES>>>(indices, weight, scales, out, n_tokens);
}